// round 9
// baseline (speedup 1.0000x reference)
#include <cuda_runtime.h>
#include <cstdint>
#include <cstddef>
#include <vector>
#include <algorithm>
#include <numeric>
#include <cmath>

// FFTLowFreqSelector: out[b,k] = mean_c log1p(|FFT2(x[b,c])|_shifted[idx_k] + 1e-12)
// 25 low-freq bins -> 4-harmonic separable DFT.
// K1 (mem-bound, ~roofline): per-column y-moments (7/column) -> scratch.
// K2 (R5): butterfly-free; one thread per (row r, x-trig j) dot product.

#define KOUT 25
#define MAXB 2048
#define DUMMY 49      // zeroed slot for absent CS/SC/SS terms

// scratch: [img][r 0..6][x 0..127], r order: C0,C1,S1,C2,S2,C3,S3
__device__ float g_ymom[(size_t)MAXB * 3 * 7 * 128];

struct Combo {
    int   iCC[KOUT], iCS[KOUT], iSC[KOUT], iSS[KOUT];
    float sgx[KOUT], sgy[KOUT];
};

// ---------------- Kernel 1: y-direction DFT moments per column ----------------
// warp w of block handles image img = blockIdx.x*4 + w; lane owns cols 4l..4l+3.
__global__ __launch_bounds__(128, 6)
void k1_ymom(const float* __restrict__ x, float* __restrict__ ym, int nimg)
{
    __shared__ float ytw[32][6];   // per y0: c1,s1,c2,s2,c3,s3
    const int tid  = threadIdx.x;
    const int lane = tid & 31;
    const int warp = tid >> 5;

    if (tid < 32) {
        float s1, c1, s2, c2, s3, c3;
        sincospif((float)tid * (1.0f / 64.0f), &s1, &c1);
        sincospif((float)tid * (2.0f / 64.0f), &s2, &c2);
        sincospif((float)tid * (3.0f / 64.0f), &s3, &c3);
        ytw[tid][0] = c1; ytw[tid][1] = s1;
        ytw[tid][2] = c2; ytw[tid][3] = s2;
        ytw[tid][4] = c3; ytw[tid][5] = s3;
    }
    __syncthreads();

    const int img = blockIdx.x * 4 + warp;
    if (img >= nimg) return;

    const float4* p = (const float4*)(x + (size_t)img * 16384) + lane;

    float Ax[7], Ay[7], Az[7], Aw[7];
    #pragma unroll
    for (int m = 0; m < 7; ++m) { Ax[m] = Ay[m] = Az[m] = Aw[m] = 0.0f; }

    // y-quadrant: rows y0, y0+32, y0+64, y0+96
    #define COLP(a0, a1, a2, a3, A)                                  \
    {                                                                \
        float u = (a0) - (a2), w = (a0) + (a2);                      \
        float v = (a1) - (a3), z = (a1) + (a3);                      \
        float d = w - z;                                             \
        A[0] += w + z;                                               \
        A[1] += u * c1 - v * s1;                                     \
        A[2] += u * s1 + v * c1;                                     \
        A[3] += d * c2;                                              \
        A[4] += d * s2;                                              \
        A[5] += u * c3 + v * s3;                                     \
        A[6] += u * s3 - v * c3;                                     \
    }

    #pragma unroll 2
    for (int q = 0; q < 32; ++q) {
        float4 a0 = p[q * 32];
        float4 a1 = p[(q + 32) * 32];
        float4 a2 = p[(q + 64) * 32];
        float4 a3 = p[(q + 96) * 32];

        const float c1 = ytw[q][0], s1 = ytw[q][1];
        const float c2 = ytw[q][2], s2 = ytw[q][3];
        const float c3 = ytw[q][4], s3 = ytw[q][5];

        COLP(a0.x, a1.x, a2.x, a3.x, Ax)
        COLP(a0.y, a1.y, a2.y, a3.y, Ay)
        COLP(a0.z, a1.z, a2.z, a3.z, Az)
        COLP(a0.w, a1.w, a2.w, a3.w, Aw)
    }
    #undef COLP

    float4* o = (float4*)(ym + (size_t)img * 7 * 128) + lane;
    #pragma unroll
    for (int m = 0; m < 7; ++m)
        o[m * 32] = make_float4(Ax[m], Ay[m], Az[m], Aw[m]);
}

// ---------------- Kernel 2: x-direction DFT as 49 dot products ----------------
// block = one batch (192 threads): channel c = tid/64, task t = tid%64 (t<49).
// task t = r*7 + j: dot(ym[img][r][:], trig_j[:]) over 128 x.
// trig rows j: 1, cos1, sin1, cos2, sin2, cos3, sin3.
__global__ __launch_bounds__(192)
void k2_xmom(const float* __restrict__ ym, float* __restrict__ out, Combo cb)
{
    __shared__ float trg[7][128];
    __shared__ float fsum[3][52];
    const int b   = blockIdx.x;
    const int tid = threadIdx.x;

    if (tid < 128) {
        float s1, c1, s2, c2, s3, c3;
        sincospif((float)tid * (1.0f / 64.0f), &s1, &c1);
        sincospif((float)tid * (2.0f / 64.0f), &s2, &c2);
        sincospif((float)tid * (3.0f / 64.0f), &s3, &c3);
        trg[0][tid] = 1.0f;
        trg[1][tid] = c1;  trg[2][tid] = s1;
        trg[3][tid] = c2;  trg[4][tid] = s2;
        trg[5][tid] = c3;  trg[6][tid] = s3;
    }
    for (int i = tid; i < 3 * 52; i += 192) (&fsum[0][0])[i] = 0.0f;
    __syncthreads();

    const int c = tid >> 6;
    const int t = tid & 63;

    if (t < 49) {
        const int r = t / 7;
        const int j = t - r * 7;
        const float4* row = (const float4*)(ym + ((size_t)(b * 3 + c) * 7 + r) * 128);
        const float4* tg  = (const float4*)trg[j];

        float a0 = 0.0f, a1 = 0.0f, a2 = 0.0f, a3 = 0.0f;
        #pragma unroll
        for (int i = 0; i < 32; ++i) {
            float4 v = row[i];
            float4 w = tg[i];
            a0 = fmaf(v.x, w.x, a0);
            a1 = fmaf(v.y, w.y, a1);
            a2 = fmaf(v.z, w.z, a2);
            a3 = fmaf(v.w, w.w, a3);
        }
        fsum[c][t] = (a0 + a1) + (a2 + a3);
    }
    __syncthreads();

    // X[fy,fx] = (CC - sx*sy*SS) - i*(sx*SC + sy*CS)
    if (tid < KOUT) {
        const float sx = cb.sgx[tid], sy = cb.sgy[tid];
        const int iCC = cb.iCC[tid], iCS = cb.iCS[tid];
        const int iSC = cb.iSC[tid], iSS = cb.iSS[tid];
        float sum = 0.0f;
        #pragma unroll
        for (int cc = 0; cc < 3; ++cc) {
            const float* F = fsum[cc];
            float re = F[iCC] - sx * sy * F[iSS];
            float im = -(sx * F[iSC] + sy * F[iCS]);
            sum += log1pf(sqrtf(re * re + im * im) + 1e-12f);
        }
        out[(size_t)b * KOUT + tid] = sum * (1.0f / 3.0f);
    }
}

// Host: replicate numpy's _lowfreq_indices exactly (stable argsort by angle,
// then stable argsort by r^2; r^2 exact in fp32 so tie classes match).
static void build_combo(Combo& cb)
{
    const int Hh = 128, Ww = 128, HW = Hh * Ww;
    std::vector<float> r2(HW), ang(HW);
    for (int y = 0; y < Hh; ++y) {
        for (int xx = 0; xx < Ww; ++xx) {
            float dy = (float)y  - 63.5f;
            float dx = (float)xx - 63.5f;
            r2[y * Ww + xx]  = dy * dy + dx * dx;
            ang[y * Ww + xx] = atan2f(dy, dx);
        }
    }
    std::vector<int> idx(HW);
    std::iota(idx.begin(), idx.end(), 0);
    std::stable_sort(idx.begin(), idx.end(),
                     [&](int a, int b) { return ang[a] < ang[b]; });
    std::stable_sort(idx.begin(), idx.end(),
                     [&](int a, int b) { return r2[a] < r2[b]; });

    for (int k = 0; k < KOUT; ++k) {
        int s  = idx[k];
        int sy = s / Ww, sx = s % Ww;
        int fy = sy - Hh / 2;
        int fx = sx - Ww / 2;
        int my = fy < 0 ? -fy : fy;
        int mx = fx < 0 ? -fx : fx;
        cb.sgy[k] = fy < 0 ? -1.0f : 1.0f;
        cb.sgx[k] = fx < 0 ? -1.0f : 1.0f;

        // task id = r*7 + j; rows r: C_my -> (my==0?0:2my-1), S_my -> 2my
        //                    cols j: C_mx -> (mx==0?0:2mx-1), S_mx -> 2mx
        int rC = (my == 0) ? 0 : (2 * my - 1);
        int rS = 2 * my;
        int jC = (mx == 0) ? 0 : (2 * mx - 1);
        int jS = 2 * mx;
        cb.iCC[k] = rC * 7 + jC;
        cb.iCS[k] = (my >= 1)            ? (rS * 7 + jC) : DUMMY;
        cb.iSC[k] = (mx >= 1)            ? (rC * 7 + jS) : DUMMY;
        cb.iSS[k] = (mx >= 1 && my >= 1) ? (rS * 7 + jS) : DUMMY;
    }
}

extern "C" void kernel_launch(void* const* d_in, const int* in_sizes, int n_in,
                              void* d_out, int out_size)
{
    const float* x   = (const float*)d_in[0];
    float*       out = (float*)d_out;

    const int CH = 3, HH = 128, WW = 128;
    const int B    = in_sizes[0] / (CH * HH * WW);
    const int nimg = B * CH;

    Combo cb;
    build_combo(cb);

    float* ym = nullptr;
    cudaGetSymbolAddress((void**)&ym, g_ymom);

    k1_ymom<<<(nimg + 3) / 4, 128>>>(x, ym, nimg);
    k2_xmom<<<B, 192>>>(ym, out, cb);
}